// round 16
// baseline (speedup 1.0000x reference)
#include <cuda_runtime.h>
#include <cuda_fp16.h>
#include <cstdint>

#define N_NODES    500000
#define D          256
#define N_IDENT    50000
#define N_ID       150000
#define N_PRIM     60000
#define N_MOD      30000
#define NT_VOCAB   120
#define PV         16
#define MV         16

// Scratch (allocation-free rule: __device__ globals).
// g_flag: 0 = interior (zero-init at load; scatter idempotent across replays).
__device__ __half g_Y[N_IDENT * D];
__device__ __half g_Wh[256 * 256];        // fp16 W_id[:, :256]
__device__ float  g_Tid[NT_VOCAB * D];
__device__ float  g_Tprim[NT_VOCAB * D];
__device__ float  g_Tmod[NT_VOCAB * D];
__device__ float  g_P[PV * D];
__device__ float  g_M[MV * D];
__device__ int    g_flag[N_NODES];

// ---------------------------------------------------------------------------
// fp32 -> fp16 conversion of W_id[:, :256] only (256x256). 32 blocks exact.
// ---------------------------------------------------------------------------
__global__ __launch_bounds__(256) void convert_w_kernel(const float* __restrict__ W)
{
    int t = blockIdx.x * 256 + threadIdx.x;
    int base = t * 8;
    int n = base >> 8;
    int k = base & 255;
    const float* src = W + (size_t)n * 512 + k;
    float4 v0 = *(const float4*)src;
    float4 v1 = *(const float4*)(src + 4);
    __half2 h0 = __floats2half2_rn(v0.x, v0.y);
    __half2 h1 = __floats2half2_rn(v0.z, v0.w);
    __half2 h2 = __floats2half2_rn(v1.x, v1.y);
    __half2 h3 = __floats2half2_rn(v1.z, v1.w);
    uint4 o = make_uint4(*(uint32_t*)&h0, *(uint32_t*)&h1,
                         *(uint32_t*)&h2, *(uint32_t*)&h3);
    *(uint4*)&g_Wh[base] = o;
}

// ---------------------------------------------------------------------------
// GEMM: Y[50000,256] = X @ W^T, mma m16n8k16 fp16 (fp32 acc).
// 512 threads, 16 warps (4M x 4N), warp tile 16x64 -> 32 acc regs/thread.
// A staged fp32 via cp.async + in-SMEM fp16 convert; B pre-converted (g_Wh).
// CTA 64x256, BK=32, double-buffered.
// ---------------------------------------------------------------------------
#define BM 64
#define BN 256
#define BK 32
#define PADK 36
#define PADH 40
#define A32BYT (BM * PADK * 4)               // 9216
#define A16OFF A32BYT
#define A16BYT (BM * PADH * 2)               // 5120
#define B16OFF (A16OFF + A16BYT)             // 14336
#define B16BYT (BN * PADH * 2)               // 20480
#define BUFB (B16OFF + B16BYT)               // 34816
#define GEMM_SMEM_BYTES (2 * BUFB)           // 69632

__device__ __forceinline__ uint32_t smem_u32(const void* p) {
    uint32_t a;
    asm("{ .reg .u64 t; cvta.to.shared.u64 t, %1; cvt.u32.u64 %0, t; }"
        : "=r"(a) : "l"(p));
    return a;
}
__device__ __forceinline__ void cp_async16(uint32_t dst, const void* src, uint32_t src_bytes) {
    asm volatile("cp.async.cg.shared.global [%0], [%1], 16, %2;"
                 :: "r"(dst), "l"(src), "r"(src_bytes) : "memory");
}
__device__ __forceinline__ void cp_commit() {
    asm volatile("cp.async.commit_group;" ::: "memory");
}
template <int N>
__device__ __forceinline__ void cp_wait() {
    asm volatile("cp.async.wait_group %0;" :: "n"(N) : "memory");
}
__device__ __forceinline__ void ldsm_x4(uint32_t* r, uint32_t addr) {
    asm volatile("ldmatrix.sync.aligned.m8n8.x4.shared.b16 {%0,%1,%2,%3}, [%4];"
                 : "=r"(r[0]), "=r"(r[1]), "=r"(r[2]), "=r"(r[3]) : "r"(addr));
}

__global__ __launch_bounds__(512) void gemm_mma_kernel(const float* __restrict__ X)
{
    extern __shared__ uint8_t smem[];

    const int tid    = threadIdx.x;
    const int wid    = tid >> 5;             // 0..15
    const int lane   = tid & 31;
    const int g      = lane >> 2;
    const int tg     = lane & 3;
    const int warp_m = wid & 3;              // 0..3
    const int warp_n = wid >> 2;             // 0..3
    const int bm     = blockIdx.x * BM;

    const uint32_t smem_base = smem_u32(smem);

    // A fp32 staging: 1 float4 per thread (64 rows x 8 segs)
    const int asrow = tid >> 3;
    const int aseg  = tid & 7;
    const int agrow = bm + asrow;
    const bool arow_ok = (agrow < N_IDENT);
    // B staging: 2 x 16B per thread (256 rows x 4 segs)
    const int bsrow = tid >> 2;              // 0..127
    const int bseg  = tid & 3;

    // ldmatrix per-lane addresses
    const int lrow  = lane & 15;
    const int lcolb = (lane >> 4) * 16;
    const uint32_t aAddr = smem_base + A16OFF +
        (uint32_t)((warp_m * 16 + lrow) * (PADH * 2) + lcolb);
    uint32_t bAddr[4];
#pragma unroll
    for (int ntp = 0; ntp < 4; ntp++)
        bAddr[ntp] = smem_base + B16OFF +
            (uint32_t)((warp_n * 64 + ntp * 16 + lrow) * (PADH * 2) + lcolb);

    float acc[8][4];
#pragma unroll
    for (int nt = 0; nt < 8; nt++)
#pragma unroll
        for (int i = 0; i < 4; i++) acc[nt][i] = 0.f;

    auto issue_loads = [&](int chunk, int buf) {
        const int k0 = chunk * BK;
        const uint32_t base = smem_base + buf * BUFB;
        // A fp32
        {
            uint32_t dst = base + (asrow * PADK + aseg * 4) * 4;
            const float* src = X + (size_t)agrow * 256 + k0 + aseg * 4;
            cp_async16(dst, src, arow_ok ? 16u : 0u);
        }
        // B fp16
#pragma unroll
        for (int i = 0; i < 2; i++) {
            int n = bsrow + i * 128;
            uint32_t dst = base + B16OFF + n * (PADH * 2) + bseg * 16;
            const __half* src = g_Wh + (size_t)n * 256 + k0 + bseg * 8;
            cp_async16(dst, src, 16u);
        }
        cp_commit();
    };

    issue_loads(0, 0);

    for (int chunk = 0; chunk < 8; chunk++) {
        if (chunk + 1 < 8) {
            issue_loads(chunk + 1, (chunk + 1) & 1);
            cp_wait<1>();
        } else {
            cp_wait<0>();
        }
        __syncthreads();

        const int buf = chunk & 1;
        // Convert A fp32 -> fp16 region (4 floats/thread)
        {
            const float* A32 = (const float*)(smem + buf * BUFB);
            __half* A16 = (__half*)(smem + buf * BUFB + A16OFF);
            float4 v = *(const float4*)(A32 + asrow * PADK + aseg * 4);
            __half2 h0 = __floats2half2_rn(v.x, v.y);
            __half2 h1 = __floats2half2_rn(v.z, v.w);
            uint2 o = make_uint2(*(uint32_t*)&h0, *(uint32_t*)&h1);
            *(uint2*)(A16 + asrow * PADH + aseg * 4) = o;
        }
        __syncthreads();

        const uint32_t boff = (uint32_t)(buf * BUFB);

#pragma unroll
        for (int ks = 0; ks < 2; ks++) {
            const uint32_t koff = boff + ks * 32;
            uint32_t a[4];
            ldsm_x4(a, aAddr + koff);
            uint32_t b[4][4];
#pragma unroll
            for (int ntp = 0; ntp < 4; ntp++)
                ldsm_x4(b[ntp], bAddr[ntp] + koff);

#pragma unroll
            for (int ntp = 0; ntp < 4; ntp++) {
                asm volatile(
                    "mma.sync.aligned.m16n8k16.row.col.f32.f16.f16.f32 "
                    "{%0,%1,%2,%3}, {%4,%5,%6,%7}, {%8,%9}, {%0,%1,%2,%3};"
                    : "+f"(acc[2*ntp][0]), "+f"(acc[2*ntp][1]),
                      "+f"(acc[2*ntp][2]), "+f"(acc[2*ntp][3])
                    : "r"(a[0]), "r"(a[1]), "r"(a[2]), "r"(a[3]),
                      "r"(b[ntp][0]), "r"(b[ntp][2]));
                asm volatile(
                    "mma.sync.aligned.m16n8k16.row.col.f32.f16.f16.f32 "
                    "{%0,%1,%2,%3}, {%4,%5,%6,%7}, {%8,%9}, {%0,%1,%2,%3};"
                    : "+f"(acc[2*ntp+1][0]), "+f"(acc[2*ntp+1][1]),
                      "+f"(acc[2*ntp+1][2]), "+f"(acc[2*ntp+1][3])
                    : "r"(a[0]), "r"(a[1]), "r"(a[2]), "r"(a[3]),
                      "r"(b[ntp][1]), "r"(b[ntp][3]));
            }
        }
        __syncthreads();
    }

    // Epilogue: half2 stores
    {
        int row0 = bm + warp_m * 16 + g;
#pragma unroll
        for (int nt = 0; nt < 8; nt++) {
            int col = warp_n * 64 + nt * 8 + tg * 2;
            if (row0 < N_IDENT)
                *(__half2*)&g_Y[(size_t)row0 * 256 + col] =
                    __floats2half2_rn(acc[nt][0], acc[nt][1]);
            if (row0 + 8 < N_IDENT)
                *(__half2*)&g_Y[(size_t)(row0 + 8) * 256 + col] =
                    __floats2half2_rn(acc[nt][2], acc[nt][3]);
        }
    }
}

// ---------------------------------------------------------------------------
// Tiny precomputes (W-row register reuse) + leaf-flag scatter, ONE kernel.
// ---------------------------------------------------------------------------
#define PRE_WARPS  12032
#define PRE_BLOCKS (PRE_WARPS / 8)                          // 1504
#define SC_TOTAL   (N_ID + N_PRIM + N_MOD)                  // 240000
#define SC_BLOCKS  ((SC_TOTAL + 255) / 256)                 // 938

__global__ __launch_bounds__(256) void precompute_kernel(
    const float* __restrict__ node_table,
    const float* __restrict__ prim_table,
    const float* __restrict__ mod_table,
    const float* __restrict__ W_id,   const float* __restrict__ b_id,
    const float* __restrict__ W_prim, const float* __restrict__ b_prim,
    const float* __restrict__ W_mod,  const float* __restrict__ b_mod,
    const int* __restrict__ id_node,   const int* __restrict__ id_ident,
    const int* __restrict__ prim_node, const int* __restrict__ prim_types,
    const int* __restrict__ mod_node,  const int* __restrict__ mod_ids)
{
    if (blockIdx.x >= PRE_BLOCKS) {
        int i = (blockIdx.x - PRE_BLOCKS) * 256 + threadIdx.x;
        if (i < N_ID) {
            g_flag[id_node[i]] = (1 << 28) | id_ident[i];
        } else if (i < N_ID + N_PRIM) {
            int j = i - N_ID;
            g_flag[prim_node[j]] = (2 << 28) | prim_types[j];
        } else if (i < SC_TOTAL) {
            int j = i - N_ID - N_PRIM;
            g_flag[mod_node[j]] = (3 << 28) | mod_ids[j];
        }
        return;
    }

    const int w    = blockIdx.x * 8 + (threadIdx.x >> 5);
    const int lane = threadIdx.x & 31;

    if (w < 11520) {
        int seg   = w / 3840;
        int r     = w - seg * 3840;
        int chunk = r >> 8;
        int o     = r & 255;

        const float* wrow;
        const float* bias;
        float* dst;
        if (seg == 0)      { wrow = W_id   + o * 512 + 256; bias = b_id;   dst = g_Tid;   }
        else if (seg == 1) { wrow = W_prim + o * 320 + 64;  bias = b_prim; dst = g_Tprim; }
        else               { wrow = W_mod  + o * 320 + 64;  bias = b_mod;  dst = g_Tmod;  }

        float wr[8];
#pragma unroll
        for (int j = 0; j < 8; j++) wr[j] = wrow[lane + 32 * j];
        float bo = bias[o];

#pragma unroll
        for (int vi = 0; vi < 8; vi++) {
            int v = chunk * 8 + vi;
            const float* trow = node_table + v * 256;
            float s = 0.f;
#pragma unroll
            for (int j = 0; j < 8; j++) s += trow[lane + 32 * j] * wr[j];
#pragma unroll
            for (int off = 16; off > 0; off >>= 1)
                s += __shfl_xor_sync(0xFFFFFFFFu, s, off);
            if (lane == 0) dst[v * D + o] = s + bo;
        }
    } else {
        int r   = w - 11520;
        int seg = r >> 8;
        int o   = r & 255;

        const float* tbl  = (seg == 0) ? prim_table : mod_table;
        const float* wrow = ((seg == 0) ? W_prim : W_mod) + o * 320;
        float* dst        = (seg == 0) ? g_P : g_M;

        float wr0 = wrow[lane];
        float wr1 = wrow[lane + 32];

#pragma unroll
        for (int v = 0; v < 16; v++) {
            const float* trow = tbl + v * 64;
            float s = trow[lane] * wr0 + trow[lane + 32] * wr1;
#pragma unroll
            for (int off = 16; off > 0; off >>= 1)
                s += __shfl_xor_sync(0xFFFFFFFFu, s, off);
            if (lane == 0) dst[v * D + o] = s;
        }
    }
}

// ---------------------------------------------------------------------------
// 16 threads per node, 4 float4 per thread: MLP=4. Streaming stores.
// ---------------------------------------------------------------------------
__global__ __launch_bounds__(256) void finalize_kernel(
    const float4* __restrict__ tbl4,
    const int* __restrict__ types,
    float4* __restrict__ out4)
{
    long long idx = (long long)blockIdx.x * 256 + threadIdx.x;
    int node = (int)(idx >> 4);
    int lane = (int)(idx & 15);

    int f = g_flag[node];
    int t = types[node];
    float4 r[4];

    if (f == 0) {
        const float4* tb = tbl4 + (size_t)t * 64 + lane;
#pragma unroll
        for (int i = 0; i < 4; i++) r[i] = tb[i * 16];
    } else {
        int kind = f >> 28;
        int src  = f & 0x0FFFFFFF;
        float4 x[4];
        const float4* yb;
        if (kind == 1) {
            const uint2* xp = (const uint2*)g_Y + (size_t)src * 64 + lane;
            uint2 raw[4];
#pragma unroll
            for (int i = 0; i < 4; i++) raw[i] = xp[i * 16];
#pragma unroll
            for (int i = 0; i < 4; i++) {
                float2 lo = __half22float2(*(const __half2*)&raw[i].x);
                float2 hi = __half22float2(*(const __half2*)&raw[i].y);
                x[i] = make_float4(lo.x, lo.y, hi.x, hi.y);
            }
            yb = (const float4*)g_Tid;
        } else {
            const float4* xb = (kind == 2) ? (const float4*)g_P : (const float4*)g_M;
            yb = (kind == 2) ? (const float4*)g_Tprim : (const float4*)g_Tmod;
            const float4* xp = xb + (size_t)src * 64 + lane;
#pragma unroll
            for (int i = 0; i < 4; i++) x[i] = xp[i * 16];
        }
        const float4* yp = yb + (size_t)t * 64 + lane;
        float4 y[4];
#pragma unroll
        for (int i = 0; i < 4; i++) y[i] = yp[i * 16];
#pragma unroll
        for (int i = 0; i < 4; i++)
            r[i] = make_float4(x[i].x + y[i].x, x[i].y + y[i].y,
                               x[i].z + y[i].z, x[i].w + y[i].w);
    }

    float4* op = out4 + (size_t)node * 64 + lane;
#pragma unroll
    for (int i = 0; i < 4; i++) __stcs(&op[i * 16], r[i]);
}

extern "C" void kernel_launch(void* const* d_in, const int* in_sizes, int n_in,
                              void* d_out, int out_size)
{
    const float* identifiers = (const float*)d_in[0];
    const float* node_table  = (const float*)d_in[1];
    const float* prim_table  = (const float*)d_in[2];
    const float* mod_table   = (const float*)d_in[3];
    const float* W_id        = (const float*)d_in[4];
    const float* b_id        = (const float*)d_in[5];
    const float* W_prim      = (const float*)d_in[6];
    const float* b_prim      = (const float*)d_in[7];
    const float* W_mod       = (const float*)d_in[8];
    const float* b_mod       = (const float*)d_in[9];
    const int*   types       = (const int*)d_in[10];
    const int*   id_ident    = (const int*)d_in[11];
    const int*   id_node     = (const int*)d_in[12];
    const int*   prim_types  = (const int*)d_in[13];
    const int*   prim_node   = (const int*)d_in[14];
    const int*   mod_ids     = (const int*)d_in[15];
    const int*   mod_node    = (const int*)d_in[16];
    float*       out         = (float*)d_out;

    static cudaStream_t s1 = nullptr;
    static cudaEvent_t evConv = nullptr, evGemm = nullptr;
    if (s1 == nullptr) {
        cudaStreamCreateWithFlags(&s1, cudaStreamNonBlocking);
        cudaEventCreateWithFlags(&evConv, cudaEventDisableTiming);
        cudaEventCreateWithFlags(&evGemm, cudaEventDisableTiming);
        cudaFuncSetAttribute(gemm_mma_kernel,
                             cudaFuncAttributeMaxDynamicSharedMemorySize,
                             GEMM_SMEM_BYTES);
    }

    // s0: tiny W fp32->fp16 conversion (gemm's only precursor)
    convert_w_kernel<<<32, 256>>>(W_id);
    cudaEventRecord(evConv, 0);

    // s1: gemm (converts X inline; overlaps precompute on s0)
    cudaStreamWaitEvent(s1, evConv, 0);
    gemm_mma_kernel<<<(N_IDENT + BM - 1) / BM, 512, GEMM_SMEM_BYTES, s1>>>(
        identifiers);
    cudaEventRecord(evGemm, s1);

    // s0: precompute + flag scatter (concurrent with gemm)
    precompute_kernel<<<PRE_BLOCKS + SC_BLOCKS, 256>>>(
        node_table, prim_table, mod_table,
        W_id, b_id, W_prim, b_prim, W_mod, b_mod,
        id_node, id_ident, prim_node, prim_types, mod_node, mod_ids);

    // Join, then the single fused output pass
    cudaStreamWaitEvent(0, evGemm, 0);
    finalize_kernel<<<31250, 256>>>((const float4*)node_table, types, (float4*)out);
}

// round 17
// speedup vs baseline: 1.0607x; 1.0607x over previous
#include <cuda_runtime.h>
#include <cuda_fp16.h>
#include <cstdint>

#define N_NODES    500000
#define D          256
#define N_IDENT    50000
#define N_ID       150000
#define N_PRIM     60000
#define N_MOD      30000
#define NT_VOCAB   120
#define PV         16
#define MV         16

// Scratch (allocation-free rule: __device__ globals).
// g_flag: 0 = interior (zero-init at load; scatter idempotent across replays).
__device__ __half g_Y[N_IDENT * D];
__device__ __half g_Wh[256 * 256];        // fp16 W_id[:, :256]
__device__ float  g_Tid[NT_VOCAB * D];
__device__ float  g_Tprim[NT_VOCAB * D];
__device__ float  g_Tmod[NT_VOCAB * D];
__device__ float  g_P[PV * D];
__device__ float  g_M[MV * D];
__device__ int    g_flag[N_NODES];

// ---------------------------------------------------------------------------
// fp32 -> fp16 conversion of W_id[:, :256] only (256x256). 32 blocks exact.
// ---------------------------------------------------------------------------
__global__ __launch_bounds__(256) void convert_w_kernel(const float* __restrict__ W)
{
    int t = blockIdx.x * 256 + threadIdx.x;
    int base = t * 8;
    int n = base >> 8;
    int k = base & 255;
    const float* src = W + (size_t)n * 512 + k;
    float4 v0 = *(const float4*)src;
    float4 v1 = *(const float4*)(src + 4);
    __half2 h0 = __floats2half2_rn(v0.x, v0.y);
    __half2 h1 = __floats2half2_rn(v0.z, v0.w);
    __half2 h2 = __floats2half2_rn(v1.x, v1.y);
    __half2 h3 = __floats2half2_rn(v1.z, v1.w);
    uint4 o = make_uint4(*(uint32_t*)&h0, *(uint32_t*)&h1,
                         *(uint32_t*)&h2, *(uint32_t*)&h3);
    *(uint4*)&g_Wh[base] = o;
}

// ---------------------------------------------------------------------------
// GEMM: Y[50000,256] = X @ W^T, mma m16n8k16 fp16 (fp32 acc).
// A staged fp32 via cp.async, converted to fp16 in-SMEM per chunk (identical
// __floats2half2_rn rounding as a standalone convert). B pre-converted (g_Wh).
// CTA 64x256, BK=32, 8 warps (2M x 4N), double buffered.
// ---------------------------------------------------------------------------
#define BM 64
#define BN 256
#define BK 32
#define PADK 36                              // fp32 A staging row (floats)
#define PADH 40                              // fp16 row (halfs, 80 B)
#define A32BYT (BM * PADK * 4)               // 9216
#define A16OFF A32BYT                        // 9216
#define A16BYT (BM * PADH * 2)               // 5120
#define B16OFF (A16OFF + A16BYT)             // 14336
#define B16BYT (BN * PADH * 2)               // 20480
#define BUFB (B16OFF + B16BYT)               // 34816
#define GEMM_SMEM_BYTES (2 * BUFB)           // 69632

__device__ __forceinline__ uint32_t smem_u32(const void* p) {
    uint32_t a;
    asm("{ .reg .u64 t; cvta.to.shared.u64 t, %1; cvt.u32.u64 %0, t; }"
        : "=r"(a) : "l"(p));
    return a;
}
__device__ __forceinline__ void cp_async16(uint32_t dst, const void* src, uint32_t src_bytes) {
    asm volatile("cp.async.cg.shared.global [%0], [%1], 16, %2;"
                 :: "r"(dst), "l"(src), "r"(src_bytes) : "memory");
}
__device__ __forceinline__ void cp_commit() {
    asm volatile("cp.async.commit_group;" ::: "memory");
}
template <int N>
__device__ __forceinline__ void cp_wait() {
    asm volatile("cp.async.wait_group %0;" :: "n"(N) : "memory");
}
__device__ __forceinline__ void ldsm_x4(uint32_t* r, uint32_t addr) {
    asm volatile("ldmatrix.sync.aligned.m8n8.x4.shared.b16 {%0,%1,%2,%3}, [%4];"
                 : "=r"(r[0]), "=r"(r[1]), "=r"(r[2]), "=r"(r[3]) : "r"(addr));
}

__global__ __launch_bounds__(256) void gemm_mma_kernel(const float* __restrict__ X)
{
    extern __shared__ uint8_t smem[];

    const int tid    = threadIdx.x;
    const int wid    = tid >> 5;
    const int lane   = tid & 31;
    const int g      = lane >> 2;
    const int tg     = lane & 3;
    const int warp_m = wid & 1;
    const int warp_n = wid >> 1;
    const int bm     = blockIdx.x * BM;

    const uint32_t smem_base = smem_u32(smem);

    const int srow = tid >> 2;
    const int sseg = tid & 3;
    const int gmrow = bm + srow;
    const bool arow_ok = (gmrow < N_IDENT);

    const int lrow  = lane & 15;
    const int lcolb = (lane >> 4) * 16;
    uint32_t aAddr[2];
#pragma unroll
    for (int mt = 0; mt < 2; mt++)
        aAddr[mt] = smem_base + A16OFF +
            (uint32_t)((warp_m * 32 + mt * 16 + lrow) * (PADH * 2) + lcolb);
    uint32_t bAddr[4];
#pragma unroll
    for (int ntp = 0; ntp < 4; ntp++)
        bAddr[ntp] = smem_base + B16OFF +
            (uint32_t)((warp_n * 64 + ntp * 16 + lrow) * (PADH * 2) + lcolb);

    float acc[2][8][4];
#pragma unroll
    for (int mt = 0; mt < 2; mt++)
#pragma unroll
        for (int nt = 0; nt < 8; nt++)
#pragma unroll
            for (int i = 0; i < 4; i++) acc[mt][nt][i] = 0.f;

    auto issue_loads = [&](int chunk, int buf) {
        const int k0 = chunk * BK;
        const uint32_t base = smem_base + buf * BUFB;
        // A fp32: 64 rows x 32 floats; 2 x 16B per thread
#pragma unroll
        for (int i = 0; i < 2; i++) {
            int sg = sseg + i * 4;
            uint32_t dst = base + (srow * PADK + sg * 4) * 4;
            const float* src = X + (size_t)gmrow * 256 + k0 + sg * 4;
            cp_async16(dst, src, arow_ok ? 16u : 0u);
        }
        // B fp16: 256 rows x 32 halfs; 4 x 16B per thread
#pragma unroll
        for (int i = 0; i < 4; i++) {
            int n = srow + i * 64;
            uint32_t dst = base + B16OFF + n * (PADH * 2) + sseg * 16;
            const __half* src = g_Wh + (size_t)n * 256 + k0 + sseg * 8;
            cp_async16(dst, src, 16u);
        }
        cp_commit();
    };

    issue_loads(0, 0);

    for (int chunk = 0; chunk < 8; chunk++) {
        if (chunk + 1 < 8) {
            issue_loads(chunk + 1, (chunk + 1) & 1);
            cp_wait<1>();
        } else {
            cp_wait<0>();
        }
        __syncthreads();

        const int buf = chunk & 1;
        // Convert A fp32 -> fp16 region (8 floats/thread)
        {
            const float* A32 = (const float*)(smem + buf * BUFB);
            __half* A16 = (__half*)(smem + buf * BUFB + A16OFF);
            float4 v0 = *(const float4*)(A32 + srow * PADK + sseg * 8);
            float4 v1 = *(const float4*)(A32 + srow * PADK + sseg * 8 + 4);
            __half2 h0 = __floats2half2_rn(v0.x, v0.y);
            __half2 h1 = __floats2half2_rn(v0.z, v0.w);
            __half2 h2 = __floats2half2_rn(v1.x, v1.y);
            __half2 h3 = __floats2half2_rn(v1.z, v1.w);
            uint4 o = make_uint4(*(uint32_t*)&h0, *(uint32_t*)&h1,
                                 *(uint32_t*)&h2, *(uint32_t*)&h3);
            *(uint4*)(A16 + srow * PADH + sseg * 8) = o;
        }
        __syncthreads();

        const uint32_t boff = (uint32_t)(buf * BUFB);

#pragma unroll
        for (int ks = 0; ks < 2; ks++) {
            const uint32_t koff = boff + ks * 32;
            uint32_t a[2][4];
#pragma unroll
            for (int mt = 0; mt < 2; mt++)
                ldsm_x4(a[mt], aAddr[mt] + koff);
            uint32_t b[4][4];
#pragma unroll
            for (int ntp = 0; ntp < 4; ntp++)
                ldsm_x4(b[ntp], bAddr[ntp] + koff);

#pragma unroll
            for (int ntp = 0; ntp < 4; ntp++) {
#pragma unroll
                for (int mt = 0; mt < 2; mt++) {
                    asm volatile(
                        "mma.sync.aligned.m16n8k16.row.col.f32.f16.f16.f32 "
                        "{%0,%1,%2,%3}, {%4,%5,%6,%7}, {%8,%9}, {%0,%1,%2,%3};"
                        : "+f"(acc[mt][2*ntp][0]), "+f"(acc[mt][2*ntp][1]),
                          "+f"(acc[mt][2*ntp][2]), "+f"(acc[mt][2*ntp][3])
                        : "r"(a[mt][0]), "r"(a[mt][1]), "r"(a[mt][2]), "r"(a[mt][3]),
                          "r"(b[ntp][0]), "r"(b[ntp][2]));
                    asm volatile(
                        "mma.sync.aligned.m16n8k16.row.col.f32.f16.f16.f32 "
                        "{%0,%1,%2,%3}, {%4,%5,%6,%7}, {%8,%9}, {%0,%1,%2,%3};"
                        : "+f"(acc[mt][2*ntp+1][0]), "+f"(acc[mt][2*ntp+1][1]),
                          "+f"(acc[mt][2*ntp+1][2]), "+f"(acc[mt][2*ntp+1][3])
                        : "r"(a[mt][0]), "r"(a[mt][1]), "r"(a[mt][2]), "r"(a[mt][3]),
                          "r"(b[ntp][1]), "r"(b[ntp][3]));
                }
            }
        }
        __syncthreads();
    }

    // Epilogue: half2 stores
#pragma unroll
    for (int mt = 0; mt < 2; mt++) {
        int row0 = bm + warp_m * 32 + mt * 16 + g;
#pragma unroll
        for (int nt = 0; nt < 8; nt++) {
            int col = warp_n * 64 + nt * 8 + tg * 2;
            if (row0 < N_IDENT)
                *(__half2*)&g_Y[(size_t)row0 * 256 + col] =
                    __floats2half2_rn(acc[mt][nt][0], acc[mt][nt][1]);
            if (row0 + 8 < N_IDENT)
                *(__half2*)&g_Y[(size_t)(row0 + 8) * 256 + col] =
                    __floats2half2_rn(acc[mt][nt][2], acc[mt][nt][3]);
        }
    }
}

// ---------------------------------------------------------------------------
// Tiny precomputes (W-row register reuse) + leaf-flag scatter, ONE kernel.
// ---------------------------------------------------------------------------
#define PRE_WARPS  12032
#define PRE_BLOCKS (PRE_WARPS / 8)                          // 1504
#define SC_TOTAL   (N_ID + N_PRIM + N_MOD)                  // 240000
#define SC_BLOCKS  ((SC_TOTAL + 255) / 256)                 // 938

__global__ __launch_bounds__(256) void precompute_kernel(
    const float* __restrict__ node_table,
    const float* __restrict__ prim_table,
    const float* __restrict__ mod_table,
    const float* __restrict__ W_id,   const float* __restrict__ b_id,
    const float* __restrict__ W_prim, const float* __restrict__ b_prim,
    const float* __restrict__ W_mod,  const float* __restrict__ b_mod,
    const int* __restrict__ id_node,   const int* __restrict__ id_ident,
    const int* __restrict__ prim_node, const int* __restrict__ prim_types,
    const int* __restrict__ mod_node,  const int* __restrict__ mod_ids)
{
    if (blockIdx.x >= PRE_BLOCKS) {
        int i = (blockIdx.x - PRE_BLOCKS) * 256 + threadIdx.x;
        if (i < N_ID) {
            g_flag[id_node[i]] = (1 << 28) | id_ident[i];
        } else if (i < N_ID + N_PRIM) {
            int j = i - N_ID;
            g_flag[prim_node[j]] = (2 << 28) | prim_types[j];
        } else if (i < SC_TOTAL) {
            int j = i - N_ID - N_PRIM;
            g_flag[mod_node[j]] = (3 << 28) | mod_ids[j];
        }
        return;
    }

    const int w    = blockIdx.x * 8 + (threadIdx.x >> 5);
    const int lane = threadIdx.x & 31;

    if (w < 11520) {
        int seg   = w / 3840;
        int r     = w - seg * 3840;
        int chunk = r >> 8;
        int o     = r & 255;

        const float* wrow;
        const float* bias;
        float* dst;
        if (seg == 0)      { wrow = W_id   + o * 512 + 256; bias = b_id;   dst = g_Tid;   }
        else if (seg == 1) { wrow = W_prim + o * 320 + 64;  bias = b_prim; dst = g_Tprim; }
        else               { wrow = W_mod  + o * 320 + 64;  bias = b_mod;  dst = g_Tmod;  }

        float wr[8];
#pragma unroll
        for (int j = 0; j < 8; j++) wr[j] = wrow[lane + 32 * j];
        float bo = bias[o];

#pragma unroll
        for (int vi = 0; vi < 8; vi++) {
            int v = chunk * 8 + vi;
            const float* trow = node_table + v * 256;
            float s = 0.f;
#pragma unroll
            for (int j = 0; j < 8; j++) s += trow[lane + 32 * j] * wr[j];
#pragma unroll
            for (int off = 16; off > 0; off >>= 1)
                s += __shfl_xor_sync(0xFFFFFFFFu, s, off);
            if (lane == 0) dst[v * D + o] = s + bo;
        }
    } else {
        int r   = w - 11520;
        int seg = r >> 8;
        int o   = r & 255;

        const float* tbl  = (seg == 0) ? prim_table : mod_table;
        const float* wrow = ((seg == 0) ? W_prim : W_mod) + o * 320;
        float* dst        = (seg == 0) ? g_P : g_M;

        float wr0 = wrow[lane];
        float wr1 = wrow[lane + 32];

#pragma unroll
        for (int v = 0; v < 16; v++) {
            const float* trow = tbl + v * 64;
            float s = trow[lane] * wr0 + trow[lane + 32] * wr1;
#pragma unroll
            for (int off = 16; off > 0; off >>= 1)
                s += __shfl_xor_sync(0xFFFFFFFFu, s, off);
            if (lane == 0) dst[v * D + o] = s;
        }
    }
}

// ---------------------------------------------------------------------------
// 16 threads per node, 4 float4 per thread: MLP=4. Streaming stores.
// ---------------------------------------------------------------------------
__global__ __launch_bounds__(256) void finalize_kernel(
    const float4* __restrict__ tbl4,
    const int* __restrict__ types,
    float4* __restrict__ out4)
{
    long long idx = (long long)blockIdx.x * 256 + threadIdx.x;
    int node = (int)(idx >> 4);
    int lane = (int)(idx & 15);

    int f = g_flag[node];
    int t = types[node];
    float4 r[4];

    if (f == 0) {
        const float4* tb = tbl4 + (size_t)t * 64 + lane;
#pragma unroll
        for (int i = 0; i < 4; i++) r[i] = tb[i * 16];
    } else {
        int kind = f >> 28;
        int src  = f & 0x0FFFFFFF;
        float4 x[4];
        const float4* yb;
        if (kind == 1) {
            const uint2* xp = (const uint2*)g_Y + (size_t)src * 64 + lane;
            uint2 raw[4];
#pragma unroll
            for (int i = 0; i < 4; i++) raw[i] = xp[i * 16];
#pragma unroll
            for (int i = 0; i < 4; i++) {
                float2 lo = __half22float2(*(const __half2*)&raw[i].x);
                float2 hi = __half22float2(*(const __half2*)&raw[i].y);
                x[i] = make_float4(lo.x, lo.y, hi.x, hi.y);
            }
            yb = (const float4*)g_Tid;
        } else {
            const float4* xb = (kind == 2) ? (const float4*)g_P : (const float4*)g_M;
            yb = (kind == 2) ? (const float4*)g_Tprim : (const float4*)g_Tmod;
            const float4* xp = xb + (size_t)src * 64 + lane;
#pragma unroll
            for (int i = 0; i < 4; i++) x[i] = xp[i * 16];
        }
        const float4* yp = yb + (size_t)t * 64 + lane;
        float4 y[4];
#pragma unroll
        for (int i = 0; i < 4; i++) y[i] = yp[i * 16];
#pragma unroll
        for (int i = 0; i < 4; i++)
            r[i] = make_float4(x[i].x + y[i].x, x[i].y + y[i].y,
                               x[i].z + y[i].z, x[i].w + y[i].w);
    }

    float4* op = out4 + (size_t)node * 64 + lane;
#pragma unroll
    for (int i = 0; i < 4; i++) __stcs(&op[i * 16], r[i]);
}

extern "C" void kernel_launch(void* const* d_in, const int* in_sizes, int n_in,
                              void* d_out, int out_size)
{
    const float* identifiers = (const float*)d_in[0];
    const float* node_table  = (const float*)d_in[1];
    const float* prim_table  = (const float*)d_in[2];
    const float* mod_table   = (const float*)d_in[3];
    const float* W_id        = (const float*)d_in[4];
    const float* b_id        = (const float*)d_in[5];
    const float* W_prim      = (const float*)d_in[6];
    const float* b_prim      = (const float*)d_in[7];
    const float* W_mod       = (const float*)d_in[8];
    const float* b_mod       = (const float*)d_in[9];
    const int*   types       = (const int*)d_in[10];
    const int*   id_ident    = (const int*)d_in[11];
    const int*   id_node     = (const int*)d_in[12];
    const int*   prim_types  = (const int*)d_in[13];
    const int*   prim_node   = (const int*)d_in[14];
    const int*   mod_ids     = (const int*)d_in[15];
    const int*   mod_node    = (const int*)d_in[16];
    float*       out         = (float*)d_out;

    static cudaStream_t s1 = nullptr;
    static cudaEvent_t evConv = nullptr, evGemm = nullptr;
    if (s1 == nullptr) {
        cudaStreamCreateWithFlags(&s1, cudaStreamNonBlocking);
        cudaEventCreateWithFlags(&evConv, cudaEventDisableTiming);
        cudaEventCreateWithFlags(&evGemm, cudaEventDisableTiming);
        cudaFuncSetAttribute(gemm_mma_kernel,
                             cudaFuncAttributeMaxDynamicSharedMemorySize,
                             GEMM_SMEM_BYTES);
    }

    // s0: tiny W fp32->fp16 conversion (gemm's only precursor)
    convert_w_kernel<<<32, 256>>>(W_id);
    cudaEventRecord(evConv, 0);

    // s1: gemm (converts X inline; overlaps precompute on s0)
    cudaStreamWaitEvent(s1, evConv, 0);
    gemm_mma_kernel<<<(N_IDENT + BM - 1) / BM, 256, GEMM_SMEM_BYTES, s1>>>(
        identifiers);
    cudaEventRecord(evGemm, s1);

    // s0: precompute + flag scatter (concurrent with gemm)
    precompute_kernel<<<PRE_BLOCKS + SC_BLOCKS, 256>>>(
        node_table, prim_table, mod_table,
        W_id, b_id, W_prim, b_prim, W_mod, b_mod,
        id_node, id_ident, prim_node, prim_types, mod_node, mod_ids);

    // Join, then the single fused output pass
    cudaStreamWaitEvent(0, evGemm, 0);
    finalize_kernel<<<31250, 256>>>((const float4*)node_table, types, (float4*)out);
}